// round 1
// baseline (speedup 1.0000x reference)
#include <cuda_runtime.h>
#include <math.h>

#define B_   512
#define T_   256
#define C_   384
#define H_   64
#define BT_  (B_ * T_)

// Scratch for Q, K, V projections (device globals: no allocation allowed)
__device__ float g_q[BT_ * H_];
__device__ float g_k[BT_ * H_];
__device__ float g_v[BT_ * H_];

// ---------------------------------------------------------------------------
// QKV projection GEMM: out[m, n] = sum_k inp[m, k] * W[k, n] + bias[n]
// A: [131072 x 384], W: [384 x 64]. grid.z: 0=V, 1=K, 2=Q.
// 64x64 tile, 256 threads, 4x4 register blocking, k-chunks of 16.
// ---------------------------------------------------------------------------
__global__ __launch_bounds__(256) void qkv_kernel(
    const float* __restrict__ inp,
    const float* __restrict__ Wv, const float* __restrict__ bv,
    const float* __restrict__ Wk, const float* __restrict__ bk,
    const float* __restrict__ Wq, const float* __restrict__ bq)
{
    __shared__ float As[64][16];
    __shared__ float Bs[16][64];

    const float* W;
    const float* bias;
    float* out;
    if (blockIdx.z == 0)      { W = Wv; bias = bv; out = g_v; }
    else if (blockIdx.z == 1) { W = Wk; bias = bk; out = g_k; }
    else                      { W = Wq; bias = bq; out = g_q; }

    const int m0  = blockIdx.x * 64;
    const int tid = threadIdx.x;
    const int tx  = tid & 15;   // 0..15 -> output col group
    const int ty  = tid >> 4;   // 0..15 -> output row group

    // load indices
    const int alr = tid >> 2;   // A row 0..63
    const int alc = tid & 3;    // A col4 0..3
    const int blr = tid >> 4;   // B row 0..15
    const int blc = tid & 15;   // B col4 0..15

    float acc[4][4] = {};

    for (int k0 = 0; k0 < C_; k0 += 16) {
        float4 a4 = *(const float4*)&inp[(size_t)(m0 + alr) * C_ + k0 + alc * 4];
        *(float4*)&As[alr][alc * 4] = a4;
        float4 b4 = *(const float4*)&W[(size_t)(k0 + blr) * H_ + blc * 4];
        *(float4*)&Bs[blr][blc * 4] = b4;
        __syncthreads();

        #pragma unroll
        for (int kk = 0; kk < 16; kk++) {
            float a[4];
            #pragma unroll
            for (int i = 0; i < 4; i++) a[i] = As[ty * 4 + i][kk];
            float4 bb = *(float4*)&Bs[kk][tx * 4];
            float b[4] = {bb.x, bb.y, bb.z, bb.w};
            #pragma unroll
            for (int i = 0; i < 4; i++)
                #pragma unroll
                for (int j = 0; j < 4; j++)
                    acc[i][j] = fmaf(a[i], b[j], acc[i][j]);
        }
        __syncthreads();
    }

    #pragma unroll
    for (int i = 0; i < 4; i++) {
        const int row = m0 + ty * 4 + i;
        #pragma unroll
        for (int j = 0; j < 4; j++) {
            const int col = tx * 4 + j;
            out[(size_t)row * H_ + col] = acc[i][j] + bias[col];
        }
    }
}

// ---------------------------------------------------------------------------
// Attention: one CTA per batch. K/Q/V fully staged in smem.
// W[t,s] = K[t]·Q[s] * scale, causal (s<=t), softmax over s, out = W·V.
// 8 warps; warp w handles rows t = w, w+8, ...
// Q padded to stride 65 so score-loop strided reads are conflict-free.
// ---------------------------------------------------------------------------
__global__ __launch_bounds__(256) void attn_kernel(float* __restrict__ out)
{
    extern __shared__ float sm[];
    float* Ks    = sm;                    // [256][64]
    float* Vs    = Ks + T_ * H_;          // [256][64]
    float* Qs    = Vs + T_ * H_;          // [256][65]  (padded)
    float* probs = Qs + T_ * 65;          // [8][256]

    const int b    = blockIdx.x;
    const int tid  = threadIdx.x;
    const int lane = tid & 31;
    const int w    = tid >> 5;

    const float* Kg = g_k + (size_t)b * T_ * H_;
    const float* Qg = g_q + (size_t)b * T_ * H_;
    const float* Vg = g_v + (size_t)b * T_ * H_;

    // Stage K, V (float4, stride-64) and Q (scalar stores, stride-65)
    for (int i = tid; i < T_ * H_ / 4; i += 256) {
        ((float4*)Ks)[i] = ((const float4*)Kg)[i];
        ((float4*)Vs)[i] = ((const float4*)Vg)[i];
        float4 q = ((const float4*)Qg)[i];
        const int s = i >> 4;          // 16 float4 per row
        const int h = (i & 15) * 4;
        float* qp = &Qs[s * 65 + h];
        qp[0] = q.x; qp[1] = q.y; qp[2] = q.z; qp[3] = q.w;
    }
    __syncthreads();

    const float scale = 0.051031036307982884f;  // 384^-0.5
    float* pr = probs + w * T_;

    for (int t = w; t < T_; t += 8) {
        const float* Kt = Ks + t * H_;

        // Pass 1: raw scores for s = lane, lane+32, ... <= t; track max
        float m = -INFINITY;
        for (int s = lane; s <= t; s += 32) {
            const float* Qse = Qs + s * 65;
            float d = 0.f;
            #pragma unroll
            for (int h = 0; h < H_; h++) d = fmaf(Kt[h], Qse[h], d);
            d *= scale;
            pr[s] = d;
            m = fmaxf(m, d);
        }
        #pragma unroll
        for (int o = 16; o > 0; o >>= 1)
            m = fmaxf(m, __shfl_xor_sync(0xffffffffu, m, o));

        // Pass 2: exp + sum
        float sum = 0.f;
        for (int s = lane; s <= t; s += 32) {
            float e = __expf(pr[s] - m);
            pr[s] = e;
            sum += e;
        }
        #pragma unroll
        for (int o = 16; o > 0; o >>= 1)
            sum += __shfl_xor_sync(0xffffffffu, sum, o);
        const float inv = 1.0f / sum;
        __syncwarp();

        // Output: each lane owns h = lane and h = lane+32
        float a0 = 0.f, a1 = 0.f;
        for (int s = 0; s <= t; s++) {
            const float p = pr[s];
            a0 = fmaf(p, Vs[s * H_ + lane], a0);
            a1 = fmaf(p, Vs[s * H_ + lane + 32], a1);
        }
        float* op = out + ((size_t)b * T_ + t) * H_;
        op[lane]      = a0 * inv;
        op[lane + 32] = a1 * inv;
        __syncwarp();
    }
}

// ---------------------------------------------------------------------------
extern "C" void kernel_launch(void* const* d_in, const int* in_sizes, int n_in,
                              void* d_out, int out_size)
{
    const float* inp = (const float*)d_in[0];
    const float* Wv  = (const float*)d_in[1];
    const float* bv  = (const float*)d_in[2];
    const float* Wk  = (const float*)d_in[3];
    const float* bk  = (const float*)d_in[4];
    const float* Wq  = (const float*)d_in[5];
    const float* bq  = (const float*)d_in[6];
    float* out = (float*)d_out;

    (void)in_sizes; (void)n_in; (void)out_size;

    // QKV projections
    dim3 grid_qkv(BT_ / 64, 1, 3);
    qkv_kernel<<<grid_qkv, 256>>>(inp, Wv, bv, Wk, bk, Wq, bq);

    // Attention
    const size_t smem = (size_t)(T_ * H_ * 2 + T_ * 65 + 8 * T_) * sizeof(float);
    cudaFuncSetAttribute(attn_kernel,
                         cudaFuncAttributeMaxDynamicSharedMemorySize, (int)smem);
    attn_kernel<<<B_, 256, smem>>>(out);
}

// round 2
// speedup vs baseline: 2.7683x; 2.7683x over previous
#include <cuda_runtime.h>
#include <math.h>
#include <stdint.h>

#define B_   512
#define T_   256
#define C_   384
#define H_   64
#define BT_  (B_ * T_)

// Scratch for Q, K, V projections (device globals: no allocation allowed)
__device__ float g_q[BT_ * H_];
__device__ float g_k[BT_ * H_];
__device__ float g_v[BT_ * H_];

// ---------------------------------------------------------------------------
// helpers: tf32 convert (round-to-nearest) + m16n8k8 tf32 mma
// ---------------------------------------------------------------------------
__device__ __forceinline__ uint32_t f2tf(float x) {
    uint32_t u;
    asm("cvt.rna.tf32.f32 %0, %1;" : "=r"(u) : "f"(x));
    return u;
}

__device__ __forceinline__ void mma8(float c[4], const uint32_t a[4], const uint32_t b[2]) {
    asm volatile(
        "mma.sync.aligned.m16n8k8.row.col.f32.tf32.tf32.f32 "
        "{%0,%1,%2,%3},{%4,%5,%6,%7},{%8,%9},{%0,%1,%2,%3};\n"
        : "+f"(c[0]), "+f"(c[1]), "+f"(c[2]), "+f"(c[3])
        : "r"(a[0]), "r"(a[1]), "r"(a[2]), "r"(a[3]), "r"(b[0]), "r"(b[1]));
}

// ---------------------------------------------------------------------------
// QKV projection GEMM (tf32 mma): out[m,n] = inp[m,:] @ W[:,n] + bias[n]
// CTA: 128x64 tile, 128 threads (4 warps, 2x2 warp grid, 64x32 warp tiles).
// bid%3 selects projection so the 3 CTAs sharing an A-tile run adjacently.
// ---------------------------------------------------------------------------
#define QKV_AS 36   // A smem row stride (pad: (4r+c)&31 conflict-free)
#define QKV_BS 72   // B smem row stride (pad: (8k+n)&31 conflict-free)

__global__ __launch_bounds__(128) void qkv_mma_kernel(
    const float* __restrict__ inp,
    const float* __restrict__ Wv, const float* __restrict__ bv,
    const float* __restrict__ Wk, const float* __restrict__ bk,
    const float* __restrict__ Wq, const float* __restrict__ bq)
{
    __shared__ uint32_t As[128 * QKV_AS];
    __shared__ uint32_t Bs[32 * QKV_BS];

    const int bid  = blockIdx.x;
    const int proj = bid % 3;
    const int m0   = (bid / 3) * 128;

    const float* W; const float* bias; float* outp;
    if (proj == 0)      { W = Wv; bias = bv; outp = g_v; }
    else if (proj == 1) { W = Wk; bias = bk; outp = g_k; }
    else                { W = Wq; bias = bq; outp = g_q; }

    const int tid  = threadIdx.x;
    const int lane = tid & 31;
    const int w    = tid >> 5;
    const int g    = lane >> 2;
    const int t4   = lane & 3;
    const int m0w  = (w >> 1) * 64;
    const int n0w  = (w & 1) * 32;

    float acc[4][4][4] = {};

    for (int k0 = 0; k0 < C_; k0 += 32) {
        // stage A tile 128x32 (tf32)
        #pragma unroll
        for (int i = 0; i < 8; i++) {
            int j = tid + 128 * i;
            int r = j >> 3, c4 = j & 7;
            float4 v = *(const float4*)&inp[(m0 + r) * C_ + k0 + c4 * 4];
            uint32_t* p = &As[r * QKV_AS + c4 * 4];
            p[0] = f2tf(v.x); p[1] = f2tf(v.y); p[2] = f2tf(v.z); p[3] = f2tf(v.w);
        }
        // stage B tile 32x64 (tf32)
        #pragma unroll
        for (int i = 0; i < 4; i++) {
            int j = tid + 128 * i;
            int r = j >> 4, c4 = j & 15;
            float4 v = *(const float4*)&W[(k0 + r) * H_ + c4 * 4];
            uint32_t* p = &Bs[r * QKV_BS + c4 * 4];
            p[0] = f2tf(v.x); p[1] = f2tf(v.y); p[2] = f2tf(v.z); p[3] = f2tf(v.w);
        }
        __syncthreads();

        #pragma unroll
        for (int ks = 0; ks < 4; ks++) {
            const int k = ks * 8;
            uint32_t a[4][4];
            #pragma unroll
            for (int fm = 0; fm < 4; fm++) {
                int rb = m0w + fm * 16;
                a[fm][0] = As[(rb + g)     * QKV_AS + k + t4];
                a[fm][1] = As[(rb + g + 8) * QKV_AS + k + t4];
                a[fm][2] = As[(rb + g)     * QKV_AS + k + t4 + 4];
                a[fm][3] = As[(rb + g + 8) * QKV_AS + k + t4 + 4];
            }
            #pragma unroll
            for (int fn = 0; fn < 4; fn++) {
                int n = n0w + fn * 8 + g;
                uint32_t b[2];
                b[0] = Bs[(k + t4)     * QKV_BS + n];
                b[1] = Bs[(k + t4 + 4) * QKV_BS + n];
                #pragma unroll
                for (int fm = 0; fm < 4; fm++)
                    mma8(acc[fm][fn], a[fm], b);
            }
        }
        __syncthreads();
    }

    // epilogue: add bias, store fp32
    #pragma unroll
    for (int fm = 0; fm < 4; fm++) {
        int r0 = m0 + m0w + fm * 16 + g;
        #pragma unroll
        for (int fn = 0; fn < 4; fn++) {
            int col = n0w + fn * 8 + 2 * t4;
            float b0f = bias[col], b1f = bias[col + 1];
            *(float2*)&outp[r0 * H_ + col] =
                make_float2(acc[fm][fn][0] + b0f, acc[fm][fn][1] + b1f);
            *(float2*)&outp[(r0 + 8) * H_ + col] =
                make_float2(acc[fm][fn][2] + b0f, acc[fm][fn][3] + b1f);
        }
    }
}

// ---------------------------------------------------------------------------
// Attention (tf32 mma, one CTA per batch, 256 threads = 8 warps):
//   S[t,s] = (scale*K[t]) · Q[s]   -> smem -> softmax (causal) -> tf32 P
//   O[t,h] = P[t,:] @ V[:,h]       (V staged transposed)
// t processed in 4 tiles of 64; s range grows causally {64,128,192,256}.
// ---------------------------------------------------------------------------
#define QS_ 68    // Q smem stride  ((4s+h)&31 conflict-free)
#define VS_ 260   // Vt/Ss stride   ((4h+s)&31 / (4t+s)&31 conflict-free)
#define KS_ 68

__global__ __launch_bounds__(256) void attn_mma_kernel(float* __restrict__ out)
{
    extern __shared__ uint32_t sm[];
    uint32_t* Qs  = sm;                   // [256][QS_]  tf32
    uint32_t* Vt  = Qs + 256 * QS_;       // [64][VS_]   tf32 (V transposed)
    uint32_t* Ks  = Vt + 64 * VS_;        // [64][KS_]   tf32 (scaled K tile)
    uint32_t* Ssu = Ks + 64 * KS_;        // [64][VS_]   scores fp32 / probs tf32
    float*    Ssf = (float*)Ssu;

    const int b    = blockIdx.x;
    const int tid  = threadIdx.x;
    const int lane = tid & 31;
    const int w    = tid >> 5;
    const int g    = lane >> 2;
    const int t4   = lane & 3;

    const float* gq = g_q + b * T_ * H_;
    const float* gk = g_k + b * T_ * H_;
    const float* gv = g_v + b * T_ * H_;
    const float scale = 0.05103103630798288f;   // 384^-0.5

    // stage Q (tf32) and V^T (tf32) once
    #pragma unroll
    for (int i = 0; i < 16; i++) {
        int j = tid + 256 * i;
        int s = j >> 4, h4 = j & 15;
        float4 q = *(const float4*)&gq[s * H_ + h4 * 4];
        *(uint4*)&Qs[s * QS_ + h4 * 4] =
            make_uint4(f2tf(q.x), f2tf(q.y), f2tf(q.z), f2tf(q.w));
        float4 v = *(const float4*)&gv[s * H_ + h4 * 4];
        Vt[(h4 * 4 + 0) * VS_ + s] = f2tf(v.x);
        Vt[(h4 * 4 + 1) * VS_ + s] = f2tf(v.y);
        Vt[(h4 * 4 + 2) * VS_ + s] = f2tf(v.z);
        Vt[(h4 * 4 + 3) * VS_ + s] = f2tf(v.w);
    }

    for (int tt = 0; tt < 4; tt++) {
        const int t0    = tt * 64;
        const int s_len = t0 + 64;

        // stage scaled K tile [64][64]
        #pragma unroll
        for (int i = 0; i < 4; i++) {
            int j = tid + 256 * i;
            int r = j >> 4, h4 = j & 15;
            float4 kv = *(const float4*)&gk[(t0 + r) * H_ + h4 * 4];
            *(uint4*)&Ks[r * KS_ + h4 * 4] =
                make_uint4(f2tf(kv.x * scale), f2tf(kv.y * scale),
                           f2tf(kv.z * scale), f2tf(kv.w * scale));
        }
        __syncthreads();   // also fences previous tile's PV reads of Ss

        // ---- S = Ks @ Qs^T  (64 x s_len), warps: 2(t) x 4(s) ----
        {
            const int wt  = w >> 2, ws = w & 3;
            const int sw  = s_len >> 2;   // s-cols per warp
            const int nf  = sw >> 3;      // n fragments (2..8)
            const int tw0 = wt * 32, sw0 = ws * sw;

            float accS[2][8][4];
            #pragma unroll
            for (int fm = 0; fm < 2; fm++)
                #pragma unroll
                for (int fn = 0; fn < 8; fn++)
                    #pragma unroll
                    for (int e = 0; e < 4; e++) accS[fm][fn][e] = 0.f;

            #pragma unroll
            for (int ks = 0; ks < 8; ks++) {
                const int k = ks * 8;
                uint32_t a[2][4];
                #pragma unroll
                for (int fm = 0; fm < 2; fm++) {
                    int rb = tw0 + fm * 16;
                    a[fm][0] = Ks[(rb + g)     * KS_ + k + t4];
                    a[fm][1] = Ks[(rb + g + 8) * KS_ + k + t4];
                    a[fm][2] = Ks[(rb + g)     * KS_ + k + t4 + 4];
                    a[fm][3] = Ks[(rb + g + 8) * KS_ + k + t4 + 4];
                }
                for (int fn = 0; fn < nf; fn++) {
                    int n = sw0 + fn * 8 + g;
                    uint32_t bb[2];
                    bb[0] = Qs[n * QS_ + k + t4];
                    bb[1] = Qs[n * QS_ + k + t4 + 4];
                    mma8(accS[0][fn], a[0], bb);
                    mma8(accS[1][fn], a[1], bb);
                }
            }
            // write raw scores
            #pragma unroll
            for (int fm = 0; fm < 2; fm++) {
                int r0 = tw0 + fm * 16 + g;
                for (int fn = 0; fn < nf; fn++) {
                    int c = sw0 + fn * 8 + 2 * t4;
                    Ssf[r0 * VS_ + c]           = accS[fm][fn][0];
                    Ssf[r0 * VS_ + c + 1]       = accS[fm][fn][1];
                    Ssf[(r0 + 8) * VS_ + c]     = accS[fm][fn][2];
                    Ssf[(r0 + 8) * VS_ + c + 1] = accS[fm][fn][3];
                }
            }
        }
        __syncthreads();

        // ---- causal softmax per row; write tf32 probs in place ----
        {
            #pragma unroll
            for (int r = 0; r < 8; r++) {
                const int t_loc  = w * 8 + r;
                const int nv     = t0 + t_loc + 1;   // valid s count
                float* row   = Ssf + t_loc * VS_;
                uint32_t* ru = Ssu + t_loc * VS_;

                float m = -1e30f;
                for (int s = lane; s < nv; s += 32) m = fmaxf(m, row[s]);
                #pragma unroll
                for (int o = 16; o > 0; o >>= 1)
                    m = fmaxf(m, __shfl_xor_sync(0xffffffffu, m, o));

                float sum = 0.f;
                for (int s = lane; s < nv; s += 32) sum += __expf(row[s] - m);
                #pragma unroll
                for (int o = 16; o > 0; o >>= 1)
                    sum += __shfl_xor_sync(0xffffffffu, sum, o);
                const float inv = 1.0f / sum;

                for (int s = lane; s < s_len; s += 32) {
                    uint32_t val = 0;
                    if (s < nv) val = f2tf(__expf(row[s] - m) * inv);
                    ru[s] = val;
                }
            }
        }
        __syncthreads();

        // ---- O = P @ V  (64 x 64), warps: 2(t) x 4(h) ----
        {
            const int wt  = w >> 2, wh = w & 3;
            const int tw0 = wt * 32, h0 = wh * 16;
            const int ksn = s_len >> 3;

            float accO[2][2][4] = {};
            for (int ks = 0; ks < ksn; ks++) {
                const int k = ks * 8;
                uint32_t a[2][4];
                #pragma unroll
                for (int fm = 0; fm < 2; fm++) {
                    int rb = tw0 + fm * 16;
                    a[fm][0] = Ssu[(rb + g)     * VS_ + k + t4];
                    a[fm][1] = Ssu[(rb + g + 8) * VS_ + k + t4];
                    a[fm][2] = Ssu[(rb + g)     * VS_ + k + t4 + 4];
                    a[fm][3] = Ssu[(rb + g + 8) * VS_ + k + t4 + 4];
                }
                #pragma unroll
                for (int fn = 0; fn < 2; fn++) {
                    int n = h0 + fn * 8 + g;
                    uint32_t bb[2];
                    bb[0] = Vt[n * VS_ + k + t4];
                    bb[1] = Vt[n * VS_ + k + t4 + 4];
                    mma8(accO[0][fn], a[0], bb);
                    mma8(accO[1][fn], a[1], bb);
                }
            }
            float* ob = out + (b * T_ + t0) * H_;
            #pragma unroll
            for (int fm = 0; fm < 2; fm++) {
                int r0 = tw0 + fm * 16 + g;
                #pragma unroll
                for (int fn = 0; fn < 2; fn++) {
                    int c = h0 + fn * 8 + 2 * t4;
                    *(float2*)&ob[r0 * H_ + c] =
                        make_float2(accO[fm][fn][0], accO[fm][fn][1]);
                    *(float2*)&ob[(r0 + 8) * H_ + c] =
                        make_float2(accO[fm][fn][2], accO[fm][fn][3]);
                }
            }
        }
    }
}

// ---------------------------------------------------------------------------
extern "C" void kernel_launch(void* const* d_in, const int* in_sizes, int n_in,
                              void* d_out, int out_size)
{
    const float* inp = (const float*)d_in[0];
    const float* Wv  = (const float*)d_in[1];
    const float* bv  = (const float*)d_in[2];
    const float* Wk  = (const float*)d_in[3];
    const float* bk  = (const float*)d_in[4];
    const float* Wq  = (const float*)d_in[5];
    const float* bq  = (const float*)d_in[6];
    float* out = (float*)d_out;

    (void)in_sizes; (void)n_in; (void)out_size;

    // QKV projections: 1024 m-tiles x 3 projections, interleaved for L2 reuse
    qkv_mma_kernel<<<(BT_ / 128) * 3, 128>>>(inp, Wv, bv, Wk, bk, Wq, bq);

    // Attention
    const int smem_bytes = (256 * QS_ + 64 * VS_ + 64 * KS_ + 64 * VS_) * 4;
    cudaFuncSetAttribute(attn_mma_kernel,
                         cudaFuncAttributeMaxDynamicSharedMemorySize, smem_bytes);
    attn_mma_kernel<<<B_, 256, smem_bytes>>>(out);
}

// round 3
// speedup vs baseline: 3.5457x; 1.2808x over previous
#include <cuda_runtime.h>
#include <math.h>
#include <stdint.h>

#define B_   512
#define T_   256
#define C_   384
#define H_   64
#define BT_  (B_ * T_)

// Scratch Q/K/V stored as tf32 bit patterns (uint32)
__device__ uint32_t g_q[BT_ * H_];
__device__ uint32_t g_k[BT_ * H_];
__device__ uint32_t g_v[BT_ * H_];

__device__ __forceinline__ uint32_t f2tf(float x) {
    uint32_t u;
    asm("cvt.rna.tf32.f32 %0, %1;" : "=r"(u) : "f"(x));
    return u;
}

__device__ __forceinline__ void mma8(float c[4], const uint32_t a[4], const uint32_t b[2]) {
    asm volatile(
        "mma.sync.aligned.m16n8k8.row.col.f32.tf32.tf32.f32 "
        "{%0,%1,%2,%3},{%4,%5,%6,%7},{%8,%9},{%0,%1,%2,%3};\n"
        : "+f"(c[0]), "+f"(c[1]), "+f"(c[2]), "+f"(c[3])
        : "r"(a[0]), "r"(a[1]), "r"(a[2]), "r"(a[3]), "r"(b[0]), "r"(b[1]));
}

// ---------------------------------------------------------------------------
// Fused QKV projection: out[m, 0:192] = inp[m,:] @ [Wv|Wk|Wq] + [bv|bk|bq]
// CTA tile 128x192, 512 threads (16 warps, 4x4 grid, warp tile 32x48).
// Register double-buffering of the next k-tile hides LDG latency.
// Outputs written as tf32 (uint32) to g_v / g_k / g_q.
// ---------------------------------------------------------------------------
#define AS_ 36    // A smem stride (128x32 tile)
#define BS_ 200   // B smem stride (32x192 tile)

__global__ __launch_bounds__(512, 1) void qkv_mma_kernel(
    const float* __restrict__ inp,
    const float* __restrict__ Wv, const float* __restrict__ bv,
    const float* __restrict__ Wk, const float* __restrict__ bk,
    const float* __restrict__ Wq, const float* __restrict__ bq)
{
    __shared__ uint32_t As[128 * AS_];
    __shared__ uint32_t Bs[32 * BS_];

    const int m0   = blockIdx.x * 128;
    const int tid  = threadIdx.x;
    const int lane = tid & 31;
    const int w    = tid >> 5;
    const int g    = lane >> 2;
    const int t4   = lane & 3;
    const int wm   = w >> 2;          // 0..3 -> 32-row slice
    const int wn   = w & 3;           // 0..3 -> 48-col slice

    // A-load mapping: 1024 float4 / 512 thr = 2 each
    const int ar[2]  = { (tid + 0)   >> 3, (tid + 512) >> 3 };
    const int ac4[2] = { tid & 7,          tid & 7 };
    // B-load mapping: 1536 float4 / 512 thr = 3 each
    int br[3], bm[3], blc4[3];
    #pragma unroll
    for (int i = 0; i < 3; i++) {
        int j = tid + 512 * i;
        br[i]   = j / 48;
        int c4  = j % 48;
        bm[i]   = c4 >> 4;
        blc4[i] = c4 & 15;
    }
    const float* Ws[3] = { Wv, Wk, Wq };

    float4 aR[2], bR[3];
    #pragma unroll
    for (int i = 0; i < 2; i++)
        aR[i] = *(const float4*)&inp[(m0 + ar[i]) * C_ + ac4[i] * 4];
    #pragma unroll
    for (int i = 0; i < 3; i++)
        bR[i] = *(const float4*)&Ws[bm[i]][br[i] * H_ + blc4[i] * 4];

    float acc[2][6][4] = {};

    for (int k0 = 0; k0 < C_; k0 += 32) {
        // commit prefetched regs to smem (tf32)
        #pragma unroll
        for (int i = 0; i < 2; i++) {
            uint32_t* p = &As[ar[i] * AS_ + ac4[i] * 4];
            *(uint4*)p = make_uint4(f2tf(aR[i].x), f2tf(aR[i].y),
                                    f2tf(aR[i].z), f2tf(aR[i].w));
        }
        #pragma unroll
        for (int i = 0; i < 3; i++) {
            uint32_t* p = &Bs[br[i] * BS_ + (bm[i] * 16 + blc4[i]) * 4];
            *(uint4*)p = make_uint4(f2tf(bR[i].x), f2tf(bR[i].y),
                                    f2tf(bR[i].z), f2tf(bR[i].w));
        }
        __syncthreads();

        // prefetch next k-tile
        if (k0 + 32 < C_) {
            #pragma unroll
            for (int i = 0; i < 2; i++)
                aR[i] = *(const float4*)&inp[(m0 + ar[i]) * C_ + k0 + 32 + ac4[i] * 4];
            #pragma unroll
            for (int i = 0; i < 3; i++)
                bR[i] = *(const float4*)&Ws[bm[i]][(k0 + 32 + br[i]) * H_ + blc4[i] * 4];
        }

        #pragma unroll
        for (int ks = 0; ks < 4; ks++) {
            const int k = ks * 8;
            uint32_t a[2][4];
            #pragma unroll
            for (int fm = 0; fm < 2; fm++) {
                int rb = wm * 32 + fm * 16;
                a[fm][0] = As[(rb + g)     * AS_ + k + t4];
                a[fm][1] = As[(rb + g + 8) * AS_ + k + t4];
                a[fm][2] = As[(rb + g)     * AS_ + k + t4 + 4];
                a[fm][3] = As[(rb + g + 8) * AS_ + k + t4 + 4];
            }
            #pragma unroll
            for (int fn = 0; fn < 6; fn++) {
                int n = wn * 48 + fn * 8 + g;
                uint32_t b[2];
                b[0] = Bs[(k + t4)     * BS_ + n];
                b[1] = Bs[(k + t4 + 4) * BS_ + n];
                mma8(acc[0][fn], a[0], b);
                mma8(acc[1][fn], a[1], b);
            }
        }
        __syncthreads();
    }

    // epilogue: bias add, tf32-round, store
    #pragma unroll
    for (int fm = 0; fm < 2; fm++) {
        int r0 = m0 + wm * 32 + fm * 16 + g;
        #pragma unroll
        for (int fn = 0; fn < 6; fn++) {
            int gcol = wn * 48 + fn * 8 + 2 * t4;
            int mtx  = gcol >> 6;
            int lc   = gcol & 63;
            uint32_t* op = (mtx == 0) ? g_v : (mtx == 1) ? g_k : g_q;
            const float* bp = (mtx == 0) ? bv : (mtx == 1) ? bk : bq;
            float b0f = bp[lc], b1f = bp[lc + 1];
            *(uint2*)&op[r0 * H_ + lc] =
                make_uint2(f2tf(acc[fm][fn][0] + b0f), f2tf(acc[fm][fn][1] + b1f));
            *(uint2*)&op[(r0 + 8) * H_ + lc] =
                make_uint2(f2tf(acc[fm][fn][2] + b0f), f2tf(acc[fm][fn][3] + b1f));
        }
    }
}

// ---------------------------------------------------------------------------
// Attention (tf32 mma, one CTA per batch, 512 threads = 16 warps):
//   S[t,s] = K[t]·Q[s] ; softmax over scaled causal scores; O = P @ V.
// t in 4 tiles of 64; s range grows {64,128,192,256}. Q, V^T staged once.
// ---------------------------------------------------------------------------
#define QS_ 68
#define VS_ 260
#define KS_ 68

__global__ __launch_bounds__(512, 1) void attn_mma_kernel(float* __restrict__ out)
{
    extern __shared__ uint32_t sm[];
    uint32_t* Qs  = sm;                   // [256][QS_]
    uint32_t* Vt  = Qs + 256 * QS_;       // [64][VS_]  (V transposed)
    uint32_t* Ks  = Vt + 64 * VS_;        // [64][KS_]
    uint32_t* Ssu = Ks + 64 * KS_;        // [64][VS_]  scores fp32 / probs tf32
    float*    Ssf = (float*)Ssu;

    const int b    = blockIdx.x;
    const int tid  = threadIdx.x;
    const int lane = tid & 31;
    const int w    = tid >> 5;            // 0..15
    const int g    = lane >> 2;
    const int t4   = lane & 3;

    const uint32_t* gq = g_q + b * T_ * H_;
    const uint32_t* gk = g_k + b * T_ * H_;
    const uint32_t* gv = g_v + b * T_ * H_;
    const float scale = 0.05103103630798288f;   // 384^-0.5

    // stage Q and V^T once (plain tf32 copies)
    #pragma unroll
    for (int i = 0; i < 8; i++) {
        int j = tid + 512 * i;            // 0..4095 float4
        int s = j >> 4, h4 = j & 15;
        uint4 q = ((const uint4*)gq)[j];
        *(uint4*)&Qs[s * QS_ + h4 * 4] = q;
        uint4 v = ((const uint4*)gv)[j];
        Vt[(h4 * 4 + 0) * VS_ + s] = v.x;
        Vt[(h4 * 4 + 1) * VS_ + s] = v.y;
        Vt[(h4 * 4 + 2) * VS_ + s] = v.z;
        Vt[(h4 * 4 + 3) * VS_ + s] = v.w;
    }

    for (int tt = 0; tt < 4; tt++) {
        const int t0    = tt * 64;
        const int s_len = t0 + 64;

        // stage K tile [64][64]
        #pragma unroll
        for (int i = 0; i < 2; i++) {
            int j = tid + 512 * i;        // 0..1023 float4
            int r = j >> 4, h4 = j & 15;
            uint4 kv = ((const uint4*)(gk + t0 * H_))[j];
            *(uint4*)&Ks[r * KS_ + h4 * 4] = kv;
        }
        __syncthreads();   // also fences prev tile's PV reads of Ss

        // ---- S = K @ Q^T  (64 x s_len), warps: 2(t) x 8(s) ----
        {
            const int wt  = w >> 3, ws = w & 7;
            const int sw  = s_len >> 3;       // cols per warp
            const int nf  = sw >> 3;          // fragments: 1..4
            const int tw0 = wt * 32, sw0 = ws * sw;

            float accS[2][4][4];
            #pragma unroll
            for (int fm = 0; fm < 2; fm++)
                #pragma unroll
                for (int fn = 0; fn < 4; fn++)
                    #pragma unroll
                    for (int e = 0; e < 4; e++) accS[fm][fn][e] = 0.f;

            #pragma unroll
            for (int ks = 0; ks < 8; ks++) {
                const int k = ks * 8;
                uint32_t a[2][4];
                #pragma unroll
                for (int fm = 0; fm < 2; fm++) {
                    int rb = tw0 + fm * 16;
                    a[fm][0] = Ks[(rb + g)     * KS_ + k + t4];
                    a[fm][1] = Ks[(rb + g + 8) * KS_ + k + t4];
                    a[fm][2] = Ks[(rb + g)     * KS_ + k + t4 + 4];
                    a[fm][3] = Ks[(rb + g + 8) * KS_ + k + t4 + 4];
                }
                for (int fn = 0; fn < nf; fn++) {
                    int n = sw0 + fn * 8 + g;
                    uint32_t bb[2];
                    bb[0] = Qs[n * QS_ + k + t4];
                    bb[1] = Qs[n * QS_ + k + t4 + 4];
                    mma8(accS[0][fn], a[0], bb);
                    mma8(accS[1][fn], a[1], bb);
                }
            }
            #pragma unroll
            for (int fm = 0; fm < 2; fm++) {
                int r0 = tw0 + fm * 16 + g;
                for (int fn = 0; fn < nf; fn++) {
                    int c = sw0 + fn * 8 + 2 * t4;
                    Ssf[r0 * VS_ + c]           = accS[fm][fn][0];
                    Ssf[r0 * VS_ + c + 1]       = accS[fm][fn][1];
                    Ssf[(r0 + 8) * VS_ + c]     = accS[fm][fn][2];
                    Ssf[(r0 + 8) * VS_ + c + 1] = accS[fm][fn][3];
                }
            }
        }
        __syncthreads();

        // ---- causal softmax, 4 rows per warp; exp once; tf32 probs in place
        {
            #pragma unroll
            for (int r = 0; r < 4; r++) {
                const int t_loc = w * 4 + r;
                const int nv    = t0 + t_loc + 1;
                float*    row   = Ssf + t_loc * VS_;
                uint32_t* ru    = Ssu + t_loc * VS_;

                float m = -1e30f;
                for (int s = lane; s < nv; s += 32) m = fmaxf(m, row[s]);
                #pragma unroll
                for (int o = 16; o > 0; o >>= 1)
                    m = fmaxf(m, __shfl_xor_sync(0xffffffffu, m, o));

                float sum = 0.f;
                for (int s = lane; s < nv; s += 32) {
                    float e = __expf((row[s] - m) * scale);
                    row[s] = e;
                    sum += e;
                }
                #pragma unroll
                for (int o = 16; o > 0; o >>= 1)
                    sum += __shfl_xor_sync(0xffffffffu, sum, o);
                const float inv = 1.0f / sum;

                for (int s = lane; s < s_len; s += 32) {
                    uint32_t val = 0;
                    if (s < nv) val = f2tf(row[s] * inv);
                    ru[s] = val;
                }
            }
        }
        __syncthreads();

        // ---- O = P @ V  (64 x 64), warps: 4(t) x 4(h), warp tile 16x16 ----
        {
            const int wt  = w >> 2, wh = w & 3;
            const int tw0 = wt * 16, h0 = wh * 16;
            const int ksn = s_len >> 3;

            float accO[2][4] = {};
            for (int ks = 0; ks < ksn; ks++) {
                const int k = ks * 8;
                uint32_t a[4];
                a[0] = Ssu[(tw0 + g)     * VS_ + k + t4];
                a[1] = Ssu[(tw0 + g + 8) * VS_ + k + t4];
                a[2] = Ssu[(tw0 + g)     * VS_ + k + t4 + 4];
                a[3] = Ssu[(tw0 + g + 8) * VS_ + k + t4 + 4];
                #pragma unroll
                for (int fn = 0; fn < 2; fn++) {
                    int n = h0 + fn * 8 + g;
                    uint32_t bb[2];
                    bb[0] = Vt[n * VS_ + k + t4];
                    bb[1] = Vt[n * VS_ + k + t4 + 4];
                    mma8(accO[fn], a, bb);
                }
            }
            float* ob = out + (b * T_ + t0) * H_;
            #pragma unroll
            for (int fn = 0; fn < 2; fn++) {
                int c = h0 + fn * 8 + 2 * t4;
                *(float2*)&ob[(tw0 + g) * H_ + c] =
                    make_float2(accO[fn][0], accO[fn][1]);
                *(float2*)&ob[(tw0 + g + 8) * H_ + c] =
                    make_float2(accO[fn][2], accO[fn][3]);
            }
        }
    }
}

// ---------------------------------------------------------------------------
extern "C" void kernel_launch(void* const* d_in, const int* in_sizes, int n_in,
                              void* d_out, int out_size)
{
    const float* inp = (const float*)d_in[0];
    const float* Wv  = (const float*)d_in[1];
    const float* bv  = (const float*)d_in[2];
    const float* Wk  = (const float*)d_in[3];
    const float* bk  = (const float*)d_in[4];
    const float* Wq  = (const float*)d_in[5];
    const float* bq  = (const float*)d_in[6];
    float* out = (float*)d_out;

    (void)in_sizes; (void)n_in; (void)out_size;

    qkv_mma_kernel<<<BT_ / 128, 512>>>(inp, Wv, bv, Wk, bk, Wq, bq);

    const int smem_bytes = (256 * QS_ + 64 * VS_ + 64 * KS_ + 64 * VS_) * 4;
    cudaFuncSetAttribute(attn_mma_kernel,
                         cudaFuncAttributeMaxDynamicSharedMemorySize, smem_bytes);
    attn_mma_kernel<<<B_, 512, smem_bytes>>>(out);
}

// round 4
// speedup vs baseline: 4.6875x; 1.3220x over previous
#include <cuda_runtime.h>
#include <math.h>
#include <stdint.h>

#define B_   512
#define T_   256
#define C_   384
#define H_   64
#define BT_  (B_ * T_)

// Scratch Q/K/V stored as tf32 bit patterns (uint32)
__device__ uint32_t g_q[BT_ * H_];
__device__ uint32_t g_k[BT_ * H_];
__device__ uint32_t g_v[BT_ * H_];

__device__ __forceinline__ uint32_t f2tf(float x) {
    uint32_t u;
    asm("cvt.rna.tf32.f32 %0, %1;" : "=r"(u) : "f"(x));
    return u;
}

__device__ __forceinline__ void mma8(float c[4], const uint32_t a[4], const uint32_t b[2]) {
    asm volatile(
        "mma.sync.aligned.m16n8k8.row.col.f32.tf32.tf32.f32 "
        "{%0,%1,%2,%3},{%4,%5,%6,%7},{%8,%9},{%0,%1,%2,%3};\n"
        : "+f"(c[0]), "+f"(c[1]), "+f"(c[2]), "+f"(c[3])
        : "r"(a[0]), "r"(a[1]), "r"(a[2]), "r"(a[3]), "r"(b[0]), "r"(b[1]));
}

#define CP16(dst_u32, src_ptr) \
    asm volatile("cp.async.cg.shared.global [%0], [%1], 16;\n" \
                 :: "r"(dst_u32), "l"(src_ptr))
#define CP_COMMIT() asm volatile("cp.async.commit_group;\n" ::)
#define CP_WAIT1()  asm volatile("cp.async.wait_group 1;\n" ::)
#define CP_WAIT0()  asm volatile("cp.async.wait_group 0;\n" ::)

// ---------------------------------------------------------------------------
// Fused QKV projection with cp.async 2-stage pipeline.
// CTA tile 128x192, 512 threads (16 warps, 4x4, warp tile 32x48).
// smem holds raw fp32; cvt.rna.tf32 applied at fragment load.
// ---------------------------------------------------------------------------
#define AS_ 36    // A smem row stride (floats)
#define BS_ 200   // B smem row stride (floats)
#define ASZ (128 * AS_)
#define BSZ (32 * BS_)

__global__ __launch_bounds__(512, 1) void qkv_mma_kernel(
    const float* __restrict__ inp,
    const float* __restrict__ Wv, const float* __restrict__ bv,
    const float* __restrict__ Wk, const float* __restrict__ bk,
    const float* __restrict__ Wq, const float* __restrict__ bq)
{
    extern __shared__ float smf[];
    float* As = smf;            // [2][ASZ]
    float* Bs = smf + 2 * ASZ;  // [2][BSZ]

    const int m0   = blockIdx.x * 128;
    const int tid  = threadIdx.x;
    const int lane = tid & 31;
    const int w    = tid >> 5;
    const int g    = lane >> 2;
    const int t4   = lane & 3;
    const int wm   = w >> 2;
    const int wn   = w & 3;

    // A: 1024 float4 / 512 thr = 2 each ; B: 1536 / 512 = 3 each
    const int ar0 = tid >> 3, ar1 = (tid + 512) >> 3, ac4 = tid & 7;
    int br[3], bm[3], blc4[3];
    #pragma unroll
    for (int i = 0; i < 3; i++) {
        int j = tid + 512 * i;
        br[i] = j / 48;
        int c4 = j % 48;
        bm[i] = c4 >> 4;
        blc4[i] = c4 & 15;
    }
    const float* Ws[3] = { Wv, Wk, Wq };

    const uint32_t sA = (uint32_t)__cvta_generic_to_shared(As);
    const uint32_t sB = (uint32_t)__cvta_generic_to_shared(Bs);

    // stage issue
    auto stage = [&](int buf, int k0) {
        uint32_t a_base = sA + buf * ASZ * 4;
        CP16(a_base + (ar0 * AS_ + ac4 * 4) * 4, &inp[(m0 + ar0) * C_ + k0 + ac4 * 4]);
        CP16(a_base + (ar1 * AS_ + ac4 * 4) * 4, &inp[(m0 + ar1) * C_ + k0 + ac4 * 4]);
        uint32_t b_base = sB + buf * BSZ * 4;
        #pragma unroll
        for (int i = 0; i < 3; i++)
            CP16(b_base + (br[i] * BS_ + (bm[i] * 16 + blc4[i]) * 4) * 4,
                 &Ws[bm[i]][(k0 + br[i]) * H_ + blc4[i] * 4]);
    };

    float acc[2][6][4] = {};

    stage(0, 0);
    CP_COMMIT();

    #pragma unroll 1
    for (int it = 0; it < 12; it++) {
        if (it + 1 < 12) { stage((it + 1) & 1, (it + 1) * 32); CP_COMMIT(); CP_WAIT1(); }
        else             { CP_WAIT0(); }
        __syncthreads();

        const float* Af = As + (it & 1) * ASZ;
        const float* Bf = Bs + (it & 1) * BSZ;

        #pragma unroll
        for (int ks = 0; ks < 4; ks++) {
            const int k = ks * 8;
            uint32_t a[2][4];
            #pragma unroll
            for (int fm = 0; fm < 2; fm++) {
                int rb = wm * 32 + fm * 16;
                a[fm][0] = f2tf(Af[(rb + g)     * AS_ + k + t4]);
                a[fm][1] = f2tf(Af[(rb + g + 8) * AS_ + k + t4]);
                a[fm][2] = f2tf(Af[(rb + g)     * AS_ + k + t4 + 4]);
                a[fm][3] = f2tf(Af[(rb + g + 8) * AS_ + k + t4 + 4]);
            }
            #pragma unroll
            for (int fn = 0; fn < 6; fn++) {
                int n = wn * 48 + fn * 8 + g;
                uint32_t b[2];
                b[0] = f2tf(Bf[(k + t4)     * BS_ + n]);
                b[1] = f2tf(Bf[(k + t4 + 4) * BS_ + n]);
                mma8(acc[0][fn], a[0], b);
                mma8(acc[1][fn], a[1], b);
            }
        }
        __syncthreads();
    }

    // epilogue: bias add, tf32-round, store
    #pragma unroll
    for (int fm = 0; fm < 2; fm++) {
        int r0 = m0 + wm * 32 + fm * 16 + g;
        #pragma unroll
        for (int fn = 0; fn < 6; fn++) {
            int gcol = wn * 48 + fn * 8 + 2 * t4;
            int mtx  = gcol >> 6;
            int lc   = gcol & 63;
            uint32_t* op = (mtx == 0) ? g_v : (mtx == 1) ? g_k : g_q;
            const float* bp = (mtx == 0) ? bv : (mtx == 1) ? bk : bq;
            float b0f = bp[lc], b1f = bp[lc + 1];
            *(uint2*)&op[r0 * H_ + lc] =
                make_uint2(f2tf(acc[fm][fn][0] + b0f), f2tf(acc[fm][fn][1] + b1f));
            *(uint2*)&op[(r0 + 8) * H_ + lc] =
                make_uint2(f2tf(acc[fm][fn][2] + b0f), f2tf(acc[fm][fn][3] + b1f));
        }
    }
}

// ---------------------------------------------------------------------------
// FlashAttention-2 style: CTA = (batch, 128-row t-block), 256 threads.
// W[t,s] = K[t]·Q[s] (keys index rows!). Stage keys tile once; stream
// query/V s-tiles. S in registers; online softmax; P->A via quad shuffles.
// ---------------------------------------------------------------------------
#define KR_ 68
#define QT_ 68
#define VT_ 72

__global__ __launch_bounds__(256, 2) void attn_fa_kernel(float* __restrict__ out)
{
    extern __shared__ uint32_t sm[];
    uint32_t* Kr = sm;                 // [128][KR_] keys rows (A operand)
    uint32_t* Qt = Kr + 128 * KR_;     // [64][QT_]  queries s-tile (B of S)
    uint32_t* Vs = Qt + 64 * QT_;      // [64][VT_]  values s-tile (B of PV)

    const int b    = blockIdx.x >> 1;
    const int t0   = (blockIdx.x & 1) * 128;
    const int tid  = threadIdx.x;
    const int lane = tid & 31;
    const int w    = tid >> 5;         // 0..7
    const int g    = lane >> 2;
    const int t4   = lane & 3;
    const int m0w  = w * 16;

    const int row0  = t0 + m0w + g;    // global t rows owned by this thread
    const int row1  = row0 + 8;
    const int tlast = t0 + m0w + 15;
    const int jmax  = tlast >> 6;

    const uint32_t* gk = g_k + b * T_ * H_;
    const uint32_t* gq = g_q + b * T_ * H_;
    const uint32_t* gv = g_v + b * T_ * H_;
    const float scale = 0.05103103630798288f;   // 384^-0.5

    // stage keys tile [128][64] (synced by first loop barrier)
    #pragma unroll
    for (int i = 0; i < 8; i++) {
        int j = tid + 256 * i;
        int r = j >> 4, h4 = j & 15;
        *(uint4*)&Kr[r * KR_ + h4 * 4] = ((const uint4*)(gk + t0 * H_))[j];
    }

    float m_run0 = -1e30f, m_run1 = -1e30f;
    float l0 = 0.f, l1 = 0.f;
    float accO[8][4] = {};

    const int njt  = (t0 + 128) >> 6;
    const int srcA = (lane & ~3) | (t4 >> 1);
    const int srcB = srcA + 2;
    const int e    = t4 & 1;

    for (int jt = 0; jt < njt; jt++) {
        const int s0 = jt * 64;

        // stage query + value s-tiles
        #pragma unroll
        for (int i = 0; i < 4; i++) {
            int j = tid + 256 * i;
            int r = j >> 4, h4 = j & 15;
            *(uint4*)&Qt[r * QT_ + h4 * 4] = ((const uint4*)(gq + s0 * H_))[j];
            *(uint4*)&Vs[r * VT_ + h4 * 4] = ((const uint4*)(gv + s0 * H_))[j];
        }
        __syncthreads();

        if (jt <= jmax) {
            const int nf = min(8, ((tlast - s0) >> 3) + 1);
            const bool need_mask = (s0 + 63 > t0 + m0w);

            // ---- S = K_rows @ Q_tile^T : accS[nf][4] ----
            float accS[8][4];
            #pragma unroll
            for (int fn = 0; fn < 8; fn++)
                #pragma unroll
                for (int e2 = 0; e2 < 4; e2++) accS[fn][e2] = 0.f;

            #pragma unroll
            for (int ks = 0; ks < 8; ks++) {
                const int k = ks * 8;
                uint32_t a[4];
                a[0] = Kr[(m0w + g)     * KR_ + k + t4];
                a[1] = Kr[(m0w + g + 8) * KR_ + k + t4];
                a[2] = Kr[(m0w + g)     * KR_ + k + t4 + 4];
                a[3] = Kr[(m0w + g + 8) * KR_ + k + t4 + 4];
                for (int fn = 0; fn < nf; fn++) {
                    int n = fn * 8 + g;
                    uint32_t bb[2];
                    bb[0] = Qt[n * QT_ + k + t4];
                    bb[1] = Qt[n * QT_ + k + t4 + 4];
                    mma8(accS[fn], a, bb);
                }
            }

            // ---- causal mask ----
            if (need_mask) {
                for (int fn = 0; fn < nf; fn++) {
                    int c = s0 + fn * 8 + 2 * t4;
                    if (c     > row0) accS[fn][0] = -1e30f;
                    if (c + 1 > row0) accS[fn][1] = -1e30f;
                    if (c     > row1) accS[fn][2] = -1e30f;
                    if (c + 1 > row1) accS[fn][3] = -1e30f;
                }
            }

            // ---- row max (quad reduce) ----
            float mt0 = -1e30f, mt1 = -1e30f;
            for (int fn = 0; fn < nf; fn++) {
                mt0 = fmaxf(mt0, fmaxf(accS[fn][0], accS[fn][1]));
                mt1 = fmaxf(mt1, fmaxf(accS[fn][2], accS[fn][3]));
            }
            #pragma unroll
            for (int o = 1; o <= 2; o <<= 1) {
                mt0 = fmaxf(mt0, __shfl_xor_sync(0xffffffffu, mt0, o));
                mt1 = fmaxf(mt1, __shfl_xor_sync(0xffffffffu, mt1, o));
            }
            float mn0 = fmaxf(m_run0, mt0);
            float mn1 = fmaxf(m_run1, mt1);
            float al0 = __expf((m_run0 - mn0) * scale);
            float al1 = __expf((m_run1 - mn1) * scale);
            m_run0 = mn0; m_run1 = mn1;

            // ---- p = exp((s-m)*scale), tile sums, tf32 in place ----
            uint32_t* accU = (uint32_t*)accS;
            float ts0 = 0.f, ts1 = 0.f;
            for (int fn = 0; fn < nf; fn++) {
                float p0 = __expf((accS[fn][0] - mn0) * scale);
                float p1 = __expf((accS[fn][1] - mn0) * scale);
                float p2 = __expf((accS[fn][2] - mn1) * scale);
                float p3 = __expf((accS[fn][3] - mn1) * scale);
                ts0 += p0 + p1; ts1 += p2 + p3;
                accU[fn * 4 + 0] = f2tf(p0);
                accU[fn * 4 + 1] = f2tf(p1);
                accU[fn * 4 + 2] = f2tf(p2);
                accU[fn * 4 + 3] = f2tf(p3);
            }
            #pragma unroll
            for (int o = 1; o <= 2; o <<= 1) {
                ts0 += __shfl_xor_sync(0xffffffffu, ts0, o);
                ts1 += __shfl_xor_sync(0xffffffffu, ts1, o);
            }
            l0 = l0 * al0 + ts0;
            l1 = l1 * al1 + ts1;

            // ---- rescale accO ----
            #pragma unroll
            for (int fn = 0; fn < 8; fn++) {
                accO[fn][0] *= al0; accO[fn][1] *= al0;
                accO[fn][2] *= al1; accO[fn][3] *= al1;
            }

            // ---- PV: A-frags from accU via quad shuffles ----
            for (int kc = 0; kc < nf; kc++) {
                uint32_t x0 = __shfl_sync(0xffffffffu, accU[kc * 4 + 0], srcA);
                uint32_t x1 = __shfl_sync(0xffffffffu, accU[kc * 4 + 1], srcA);
                uint32_t y0 = __shfl_sync(0xffffffffu, accU[kc * 4 + 2], srcA);
                uint32_t y1 = __shfl_sync(0xffffffffu, accU[kc * 4 + 3], srcA);
                uint32_t x2 = __shfl_sync(0xffffffffu, accU[kc * 4 + 0], srcB);
                uint32_t x3 = __shfl_sync(0xffffffffu, accU[kc * 4 + 1], srcB);
                uint32_t y2 = __shfl_sync(0xffffffffu, accU[kc * 4 + 2], srcB);
                uint32_t y3 = __shfl_sync(0xffffffffu, accU[kc * 4 + 3], srcB);
                uint32_t a[4];
                a[0] = e ? x1 : x0;   // (row g,   col kc*8 + t4)
                a[1] = e ? y1 : y0;   // (row g+8, col kc*8 + t4)
                a[2] = e ? x3 : x2;   // (row g,   col kc*8 + t4+4)
                a[3] = e ? y3 : y2;   // (row g+8, col kc*8 + t4+4)
                const int k = kc * 8;
                #pragma unroll
                for (int fn = 0; fn < 8; fn++) {
                    int n = fn * 8 + g;
                    uint32_t bb[2];
                    bb[0] = Vs[(k + t4)     * VT_ + n];
                    bb[1] = Vs[(k + t4 + 4) * VT_ + n];
                    mma8(accO[fn], a, bb);
                }
            }
        }
        __syncthreads();
    }

    // epilogue: normalize + store
    const float inv0 = 1.0f / l0;
    const float inv1 = 1.0f / l1;
    float* ob = out + (size_t)b * T_ * H_;
    #pragma unroll
    for (int fn = 0; fn < 8; fn++) {
        int c = fn * 8 + 2 * t4;
        *(float2*)&ob[row0 * H_ + c] =
            make_float2(accO[fn][0] * inv0, accO[fn][1] * inv0);
        *(float2*)&ob[row1 * H_ + c] =
            make_float2(accO[fn][2] * inv1, accO[fn][3] * inv1);
    }
}

// ---------------------------------------------------------------------------
extern "C" void kernel_launch(void* const* d_in, const int* in_sizes, int n_in,
                              void* d_out, int out_size)
{
    const float* inp = (const float*)d_in[0];
    const float* Wv  = (const float*)d_in[1];
    const float* bv  = (const float*)d_in[2];
    const float* Wk  = (const float*)d_in[3];
    const float* bk  = (const float*)d_in[4];
    const float* Wq  = (const float*)d_in[5];
    const float* bq  = (const float*)d_in[6];
    float* out = (float*)d_out;

    (void)in_sizes; (void)n_in; (void)out_size;

    const int qkv_smem = (2 * ASZ + 2 * BSZ) * 4;
    cudaFuncSetAttribute(qkv_mma_kernel,
                         cudaFuncAttributeMaxDynamicSharedMemorySize, qkv_smem);
    qkv_mma_kernel<<<BT_ / 128, 512, qkv_smem>>>(inp, Wv, bv, Wk, bk, Wq, bq);

    const int attn_smem = (128 * KR_ + 64 * QT_ + 64 * VT_) * 4;
    cudaFuncSetAttribute(attn_fa_kernel,
                         cudaFuncAttributeMaxDynamicSharedMemorySize, attn_smem);
    attn_fa_kernel<<<B_ * 2, 256, attn_smem>>>(out);
}